// round 16
// baseline (speedup 1.0000x reference)
#include <cuda_runtime.h>
#include <cuda_bf16.h>
#include <cstdint>

// DNN_84026740179139: embedding-bag mean + 3x[64x64 Linear+ReLU].
// R16: OVERLAPPED producer-consumer single kernel.
//   - grid 1152 = 1024 gather-role blocks (R13 body) + 128 MLP-role blocks
//     (R10 tile 4rx8d @ 256thr, RPB=128). Producers have lower bids -> run first;
//     consumers spin (nanosleep) on per-producer flags, overlap with gather tail.
//   - flags reset per launch via cudaMemsetAsync (graph-capturable).
//   - MLP smem (sW 16K + sXt 33K = 50176B) dynamic; sIdx 3.3K static.

#define BATCH   16384
#define DIMS    64
#define NNZ     50

typedef unsigned long long u64;

__device__ __forceinline__ u64 ffma2(u64 a, u64 b, u64 c) {
    u64 d; asm("fma.rn.f32x2 %0, %1, %2, %3;" : "=l"(d) : "l"(a), "l"(b), "l"(c)); return d;
}
__device__ __forceinline__ u64 add2(u64 a, u64 b) {
    u64 d; asm("add.rn.f32x2 %0, %1, %2;" : "=l"(d) : "l"(a), "l"(b)); return d;
}
__device__ __forceinline__ u64 mul2(u64 a, u64 b) {
    u64 d; asm("mul.rn.f32x2 %0, %1, %2;" : "=l"(d) : "l"(a), "l"(b)); return d;
}
__device__ __forceinline__ u64 pack2(float x, float y) {
    u64 d; asm("mov.b64 %0, {%1, %2};" : "=l"(d) : "f"(x), "f"(y)); return d;
}
__device__ __forceinline__ void unpack2(u64 d, float& x, float& y) {
    asm("mov.b64 {%0, %1}, %2;" : "=f"(x), "=f"(y) : "l"(d));
}

__device__ float g_X[BATCH * DIMS];     // 4MB pooled embeddings
__device__ int   g_flags[1024];         // per-gather-block done flags

#define G_RPB    16                 // gather rows per block
#define G_BLKS   (BATCH / G_RPB)    // 1024
#define M_RPB    128                // mlp rows per block
#define M_BLKS   (BATCH / M_RPB)    // 128
#define THR      256
#define GRID     (G_BLKS + M_BLKS)  // 1152
#define IDXS     52                 // padded idx row stride (13 int4)
#define XTS      132                // sXt row stride (mult of 4)
#define SMEM_BYTES ((DIMS * DIMS + DIMS * XTS) * 4)   // 50176 B

__global__ __launch_bounds__(THR) void fused_overlap_kernel(
    const float* __restrict__ emb,
    const int*   __restrict__ fidx,
    const float* __restrict__ W0, const float* __restrict__ b0,
    const float* __restrict__ W1, const float* __restrict__ b1,
    const float* __restrict__ b2, const float* __restrict__ W2,
    float* __restrict__ out)
{
    extern __shared__ float dsm[];         // mlp role: sW | sXt
    __shared__ int sIdx[G_RPB * IDXS];     // gather role: 3.3 KB

    const int tid = threadIdx.x;
    const int bid = blockIdx.x;

    if (bid < G_BLKS) {
        // ================= GATHER ROLE (R13 body) =================
        {
            const int* src = fidx + bid * G_RPB * NNZ;
            #pragma unroll
            for (int s = 0; s < 4; s++) {
                const int i = tid + s * THR;
                if (i < G_RPB * NNZ) {
                    const int r = i / NNZ;
                    const int j = i - r * NNZ;
                    sIdx[r * IDXS + j] = src[i];
                }
            }
        }
        __syncthreads();

        const int warp = tid >> 5;
        const int lane = tid & 31;
        const int half = lane >> 4;
        const int c    = lane & 15;
        const int lrow = 2 * warp + half;

        const ulonglong2* emb2 = (const ulonglong2*)emb;
        const int4* idx4 = (const int4*)(sIdx + lrow * IDXS);
        u64 a01 = 0ull, a23 = 0ull;

        #pragma unroll 3
        for (int g = 0; g < 12; g++) {
            const int4 id = idx4[g];
            const ulonglong2 v0 = __ldg(&emb2[(size_t)id.x * 16 + c]);
            const ulonglong2 v1 = __ldg(&emb2[(size_t)id.y * 16 + c]);
            const ulonglong2 v2 = __ldg(&emb2[(size_t)id.z * 16 + c]);
            const ulonglong2 v3 = __ldg(&emb2[(size_t)id.w * 16 + c]);
            a01 = add2(a01, v0.x); a23 = add2(a23, v0.y);
            a01 = add2(a01, v1.x); a23 = add2(a23, v1.y);
            a01 = add2(a01, v2.x); a23 = add2(a23, v2.y);
            a01 = add2(a01, v3.x); a23 = add2(a23, v3.y);
        }
        {
            const int4 id = idx4[12];
            const ulonglong2 v0 = __ldg(&emb2[(size_t)id.x * 16 + c]);
            const ulonglong2 v1 = __ldg(&emb2[(size_t)id.y * 16 + c]);
            a01 = add2(a01, v0.x); a23 = add2(a23, v0.y);
            a01 = add2(a01, v1.x); a23 = add2(a23, v1.y);
        }

        const u64 inv2 = pack2(1.0f / NNZ, 1.0f / NNZ);
        a01 = mul2(a01, inv2);
        a23 = mul2(a23, inv2);

        float f0, f1, f2, f3;
        unpack2(a01, f0, f1);
        unpack2(a23, f2, f3);
        const int grow = bid * G_RPB + lrow;
        *(float4*)(g_X + (size_t)grow * DIMS + 4 * c) = make_float4(f0, f1, f2, f3);

        // publish
        __syncthreads();
        __threadfence();
        if (tid == 0) atomicExch(&g_flags[bid], 1);
        return;
    }

    // ================= MLP ROLE (R10 body @ 256thr, RPB=128) =================
    const int m = bid - G_BLKS;            // 0..127
    float* sW  = dsm;                      // [64][64]
    float* sXt = dsm + DIMS * DIMS;        // [64][XTS]

    // wait for the 8 producer blocks covering rows [128m, 128m+128)
    if (tid < 8) {
        while (atomicAdd(&g_flags[8 * m + tid], 0) == 0) __nanosleep(64);
    }
    __syncthreads();

    // ---- stage W0 (4 float4/thread) ----
    {
        const float4* src = (const float4*)W0;
        float4*       dst = (float4*)sW;
        #pragma unroll
        for (int s = 0; s < 4; s++)
            dst[tid + s * THR] = src[tid + s * THR];
    }

    // ---- load X tile [128 x 64] (L2 reads, 8 float4/thread) + transpose ----
    {
        const float4* X4 = (const float4*)(g_X + (size_t)m * M_RPB * DIMS);
        #pragma unroll
        for (int s = 0; s < 8; s++) {
            const int idx = tid + s * THR;          // 0..2047
            const int row = idx >> 4;               // 0..127
            const int cg  = idx & 15;               // dims 4cg..4cg+3
            const float4 v = __ldcg(&X4[idx]);
            sXt[(4 * cg + 0) * XTS + row] = v.x;
            sXt[(4 * cg + 1) * XTS + row] = v.y;
            sXt[(4 * cg + 2) * XTS + row] = v.z;
            sXt[(4 * cg + 3) * XTS + row] = v.w;
        }
    }
    __syncthreads();

    // ---- GEMM: thread tile = 4 rows (2 packed pairs) x 8 dims ----
    const int r0 = 4 * (tid & 31);          // rows 0..127
    const int d0 = 8 * (tid >> 5);          // dims, warp-uniform

    const float* Wn[3] = {W0, W1, W2};
    const float* bn[3] = {b0, b1, b2};

    u64 y2[2][8];   // y2[p][dd] = (y[r0+2p][d0+dd], y[r0+2p+1][d0+dd])

    #pragma unroll
    for (int l = 0; l < 3; l++) {
        {
            const float4 ba = __ldg((const float4*)(bn[l]) + (d0 >> 2));
            const float4 bb = __ldg((const float4*)(bn[l]) + (d0 >> 2) + 1);
            y2[0][0] = pack2(ba.x, ba.x); y2[0][1] = pack2(ba.y, ba.y);
            y2[0][2] = pack2(ba.z, ba.z); y2[0][3] = pack2(ba.w, ba.w);
            y2[0][4] = pack2(bb.x, bb.x); y2[0][5] = pack2(bb.y, bb.y);
            y2[0][6] = pack2(bb.z, bb.z); y2[0][7] = pack2(bb.w, bb.w);
            #pragma unroll
            for (int dd = 0; dd < 8; dd++) y2[1][dd] = y2[0][dd];
        }

        #pragma unroll 8
        for (int k = 0; k < DIMS; k++) {
            const ulonglong2 xv = *(const ulonglong2*)(sXt + k * XTS + r0);
            const float4 wa = *(const float4*)(sW + k * DIMS + d0);
            const float4 wb = *(const float4*)(sW + k * DIMS + d0 + 4);
            u64 w2[8];
            w2[0] = pack2(wa.x, wa.x); w2[1] = pack2(wa.y, wa.y);
            w2[2] = pack2(wa.z, wa.z); w2[3] = pack2(wa.w, wa.w);
            w2[4] = pack2(wb.x, wb.x); w2[5] = pack2(wb.y, wb.y);
            w2[6] = pack2(wb.z, wb.z); w2[7] = pack2(wb.w, wb.w);
            #pragma unroll
            for (int dd = 0; dd < 8; dd++) {
                y2[0][dd] = ffma2(xv.x, w2[dd], y2[0][dd]);
                y2[1][dd] = ffma2(xv.y, w2[dd], y2[1][dd]);
            }
        }

        // ReLU
        #pragma unroll
        for (int p = 0; p < 2; p++)
            #pragma unroll
            for (int dd = 0; dd < 8; dd++) {
                float a, b;
                unpack2(y2[p][dd], a, b);
                y2[p][dd] = pack2(fmaxf(a, 0.f), fmaxf(b, 0.f));
            }

        if (l < 2) {
            __syncthreads();
            {
                const float4* src = (const float4*)Wn[l + 1];
                float4*       dst = (float4*)sW;
                #pragma unroll
                for (int s = 0; s < 4; s++)
                    dst[tid + s * THR] = src[tid + s * THR];
            }
            #pragma unroll
            for (int p = 0; p < 2; p++)
                #pragma unroll
                for (int dd = 0; dd < 8; dd++)
                    *(u64*)(sXt + (d0 + dd) * XTS + r0 + 2 * p) = y2[p][dd];
            __syncthreads();
        }
    }

    // ---- store out[B,64]: 4 rows x 8 dims ----
    #pragma unroll
    for (int p = 0; p < 2; p++) {
        float lo[8], hi[8];
        #pragma unroll
        for (int dd = 0; dd < 8; dd++) unpack2(y2[p][dd], lo[dd], hi[dd]);
        const size_t gr = (size_t)m * M_RPB + r0 + 2 * p;
        *(float4*)(out + gr * DIMS + d0)           = make_float4(lo[0], lo[1], lo[2], lo[3]);
        *(float4*)(out + gr * DIMS + d0 + 4)       = make_float4(lo[4], lo[5], lo[6], lo[7]);
        *(float4*)(out + (gr + 1) * DIMS + d0)     = make_float4(hi[0], hi[1], hi[2], hi[3]);
        *(float4*)(out + (gr + 1) * DIMS + d0 + 4) = make_float4(hi[4], hi[5], hi[6], hi[7]);
    }
}

extern "C" void kernel_launch(void* const* d_in, const int* in_sizes, int n_in,
                              void* d_out, int out_size)
{
    // Resolve inputs by element count:
    //   emb_table 6400000 f32; feature_indices 819200 i32 (first occurrence);
    //   W* 4096 f32 in order; b* 64 f32 in order.
    const float* emb  = nullptr;
    const int*   fidx = nullptr;
    const float* W[3] = {nullptr, nullptr, nullptr};
    const float* b[3] = {nullptr, nullptr, nullptr};
    int wi = 0, bi = 0;

    for (int i = 0; i < n_in; i++) {
        const int sz = in_sizes[i];
        if (sz == 100000 * 64) {
            emb = (const float*)d_in[i];
        } else if (sz == BATCH * NNZ) {
            if (!fidx) fidx = (const int*)d_in[i];
        } else if (sz == DIMS * DIMS) {
            if (wi < 3) W[wi++] = (const float*)d_in[i];
        } else if (sz == DIMS) {
            if (bi < 3) b[bi++] = (const float*)d_in[i];
        }
    }

    float* out = (float*)d_out;

    // reset flags (graph-capturable stream op; no allocation)
    void* flags_ptr = nullptr;
    cudaGetSymbolAddress(&flags_ptr, g_flags);
    cudaMemsetAsync(flags_ptr, 0, sizeof(int) * 1024);

    // 50.2KB dynamic smem opt-in (host attribute; capture-safe)
    cudaFuncSetAttribute(fused_overlap_kernel,
                         cudaFuncAttributeMaxDynamicSharedMemorySize,
                         SMEM_BYTES);

    fused_overlap_kernel<<<GRID, THR, SMEM_BYTES>>>(
        emb, fidx, W[0], b[0], W[1], b[1], b[2], W[2], out);
}